// round 8
// baseline (speedup 1.0000x reference)
#include <cuda_runtime.h>
#include <cuda_bf16.h>
#include <cstdint>
#include <math.h>

#define D_MODEL 384
#define N_HEADS 8
#define HEAD_DIM 48
#define BATCH 2
#define NTOK 2048
#define TOTAL_TOK (BATCH * NTOK)
#define QKV_COLS (3 * D_MODEL)

// Scratch (allocation-free)
__device__ float g_qkv[TOTAL_TOK * QKV_COLS];
__device__ float g_attn[TOTAL_TOK * D_MODEL];

// ---------------------------------------------------------------------------
// helpers
// ---------------------------------------------------------------------------
__device__ __forceinline__ void mma_bf16(float* d, const uint32_t* a, const uint32_t* b) {
    asm volatile(
        "mma.sync.aligned.m16n8k16.row.col.f32.bf16.bf16.f32 "
        "{%0,%1,%2,%3}, {%4,%5,%6,%7}, {%8,%9}, {%0,%1,%2,%3};"
        : "+f"(d[0]), "+f"(d[1]), "+f"(d[2]), "+f"(d[3])
        : "r"(a[0]), "r"(a[1]), "r"(a[2]), "r"(a[3]), "r"(b[0]), "r"(b[1]));
}

__device__ __forceinline__ uint32_t pack_bf16(float x, float y) {
    uint32_t r; asm("cvt.rn.bf16x2.f32 %0, %1, %2;" : "=r"(r) : "f"(y), "f"(x)); return r;
}
__device__ __forceinline__ void split_pair(float v0, float v1, uint32_t& hi, uint32_t& lo) {
    hi = pack_bf16(v0, v1);
    float h0 = __uint_as_float(hi << 16);
    float h1 = __uint_as_float(hi & 0xFFFF0000u);
    lo = pack_bf16(v0 - h0, v1 - h1);
}

__device__ __forceinline__ float sqrt_approx(float x) {
    float r; asm("sqrt.approx.f32 %0, %1;" : "=f"(r) : "f"(x)); return r;
}
__device__ __forceinline__ float ex2_approx(float x) {
    float r; asm("ex2.approx.f32 %0, %1;" : "=f"(r) : "f"(x)); return r;
}

// ---------------------------------------------------------------------------
// 3xBF16 tensor-core GEMM with bias, latency-engineered:
//  - register prefetch double-buffering of the k-tile (LDG under MMA)
//  - MMA chain distance 8 (accumulator rotation)
// C = A @ B + bias. BM=128, BN=64, BK=32; 256 threads; warp tile 32x32.
// K must be a multiple of 32 and >= 64.
// ---------------------------------------------------------------------------
#define GBM 128
#define GBN 64
#define GBK 32
#define ASTR 20
#define BSTR 20

__global__ __launch_bounds__(256, 2)
void gemm_bf16x3_kernel(const float* __restrict__ A, const float* __restrict__ B,
                        const float* __restrict__ bias, float* __restrict__ C,
                        int M, int N, int K)
{
    __shared__ uint32_t sAh[GBM * ASTR];
    __shared__ uint32_t sAl[GBM * ASTR];
    __shared__ uint32_t sBh[GBN * BSTR];
    __shared__ uint32_t sBl[GBN * BSTR];

    const int tid = threadIdx.x;
    const int w = tid >> 5;
    const int lane = tid & 31;
    const int g = lane >> 2;
    const int t = lane & 3;
    const int wm = w >> 1;
    const int wn = w & 1;
    const int row0 = blockIdx.y * GBM;
    const int col0 = blockIdx.x * GBN;

    // prefetch maps (compile-time per ii):
    // A: i = tid + 256*ii (ii<4) over GBM*8 float4s: r=i>>3, j=i&7
    // B: i = tid + 256*ii (ii<4) over GBN*16 pairs: n=i&63, kp=i>>6
    float4 pA[4];
    float2 pB[4];

    // initial prefetch (k0 = 0)
    #pragma unroll
    for (int ii = 0; ii < 4; ii++) {
        const int i = tid + 256 * ii;
        const int r = i >> 3, j = i & 7;
        pA[ii] = __ldg(reinterpret_cast<const float4*>(A + (size_t)(row0 + r) * K + 4 * j));
    }
    #pragma unroll
    for (int ii = 0; ii < 4; ii++) {
        const int i = tid + 256 * ii;
        const int n = i & 63, kp = i >> 6;
        pB[ii].x = __ldg(B + (size_t)(2 * kp) * N + col0 + n);
        pB[ii].y = __ldg(B + (size_t)(2 * kp + 1) * N + col0 + n);
    }

    float acc[2][4][4];
    #pragma unroll
    for (int mt = 0; mt < 2; mt++)
        #pragma unroll
        for (int nb = 0; nb < 4; nb++)
            #pragma unroll
            for (int e = 0; e < 4; e++) acc[mt][nb][e] = 0.f;

    for (int k0 = 0; k0 < K; k0 += GBK) {
        __syncthreads();
        // ---- STS: split prefetched tile into smem ----
        #pragma unroll
        for (int ii = 0; ii < 4; ii++) {
            const int i = tid + 256 * ii;
            const int r = i >> 3, j = i & 7;
            uint32_t h0, l0, h1, l1;
            split_pair(pA[ii].x, pA[ii].y, h0, l0);
            split_pair(pA[ii].z, pA[ii].w, h1, l1);
            const int base = r * ASTR + 2 * j;
            sAh[base] = h0; sAh[base + 1] = h1;
            sAl[base] = l0; sAl[base + 1] = l1;
        }
        #pragma unroll
        for (int ii = 0; ii < 4; ii++) {
            const int i = tid + 256 * ii;
            const int n = i & 63, kp = i >> 6;
            uint32_t hh, ll;
            split_pair(pB[ii].x, pB[ii].y, hh, ll);
            sBh[n * BSTR + kp] = hh;
            sBl[n * BSTR + kp] = ll;
        }
        __syncthreads();

        // ---- prefetch next k-tile (overlapped with MMAs below) ----
        if (k0 + GBK < K) {
            const int k1 = k0 + GBK;
            #pragma unroll
            for (int ii = 0; ii < 4; ii++) {
                const int i = tid + 256 * ii;
                const int r = i >> 3, j = i & 7;
                pA[ii] = __ldg(reinterpret_cast<const float4*>(A + (size_t)(row0 + r) * K + k1 + 4 * j));
            }
            #pragma unroll
            for (int ii = 0; ii < 4; ii++) {
                const int i = tid + 256 * ii;
                const int n = i & 63, kp = i >> 6;
                pB[ii].x = __ldg(B + (size_t)(k1 + 2 * kp) * N + col0 + n);
                pB[ii].y = __ldg(B + (size_t)(k1 + 2 * kp + 1) * N + col0 + n);
            }
        }

        // ---- MMAs: chain distance 8 via accumulator rotation ----
        #pragma unroll
        for (int kc = 0; kc < 2; kc++) {
            uint32_t ah[2][4], al[2][4];
            #pragma unroll
            for (int mt = 0; mt < 2; mt++) {
                const int rA = (32 * wm + 16 * mt + g) * ASTR + 8 * kc;
                const int rB = rA + 8 * ASTR;
                ah[mt][0] = sAh[rA + t];     al[mt][0] = sAl[rA + t];
                ah[mt][1] = sAh[rB + t];     al[mt][1] = sAl[rB + t];
                ah[mt][2] = sAh[rA + t + 4]; al[mt][2] = sAl[rA + t + 4];
                ah[mt][3] = sAh[rB + t + 4]; al[mt][3] = sAl[rB + t + 4];
            }
            uint32_t bh_[4][2], bl_[4][2];
            #pragma unroll
            for (int nb = 0; nb < 4; nb++) {
                const int nbase = (32 * wn + 8 * nb + g) * BSTR + 8 * kc;
                bh_[nb][0] = sBh[nbase + t];
                bh_[nb][1] = sBh[nbase + t + 4];
                bl_[nb][0] = sBl[nbase + t];
                bl_[nb][1] = sBl[nbase + t + 4];
            }
            #pragma unroll
            for (int nb = 0; nb < 4; nb++) mma_bf16(acc[0][nb], ah[0], bh_[nb]);
            #pragma unroll
            for (int nb = 0; nb < 4; nb++) mma_bf16(acc[1][nb], ah[1], bh_[nb]);
            #pragma unroll
            for (int nb = 0; nb < 4; nb++) mma_bf16(acc[0][nb], al[0], bh_[nb]);
            #pragma unroll
            for (int nb = 0; nb < 4; nb++) mma_bf16(acc[1][nb], al[1], bh_[nb]);
            #pragma unroll
            for (int nb = 0; nb < 4; nb++) mma_bf16(acc[0][nb], ah[0], bl_[nb]);
            #pragma unroll
            for (int nb = 0; nb < 4; nb++) mma_bf16(acc[1][nb], ah[1], bl_[nb]);
        }
    }

    #pragma unroll
    for (int mt = 0; mt < 2; mt++) {
        const int rA = row0 + 32 * wm + 16 * mt + g;
        #pragma unroll
        for (int nb = 0; nb < 4; nb++) {
            const int c = col0 + 32 * wn + 8 * nb + 2 * t;
            const float bx = bias[c], by = bias[c + 1];
            *reinterpret_cast<float2*>(C + (size_t)rA * N + c) =
                make_float2(acc[mt][nb][0] + bx, acc[mt][nb][1] + by);
            *reinterpret_cast<float2*>(C + (size_t)(rA + 8) * N + c) =
                make_float2(acc[mt][nb][2] + bx, acc[mt][nb][3] + by);
        }
    }
}

// ---------------------------------------------------------------------------
// Fused attention (verified R7, unchanged): prefetch double-buffering,
// MMA chain distance 4, softmax interleaved with PV.
// ---------------------------------------------------------------------------
#define TJ 64
#define MQ 256
#define N_ITERS (NTOK / TJ)
#define KSTR 28
#define VSTR 36
#define LOG2E 1.4426950408889634f

__global__ __launch_bounds__(256, 1)
void attn_mma_kernel(const float* __restrict__ qkv, const float* __restrict__ coords,
                     const float* __restrict__ W_dist, const float* __restrict__ b_dist,
                     float* __restrict__ out)
{
    __shared__ uint32_t sKh[TJ * KSTR];
    __shared__ uint32_t sKl[TJ * KSTR];
    __shared__ uint32_t sVh[HEAD_DIM * VSTR];
    __shared__ uint32_t sVl[HEAD_DIM * VSTR];
    __shared__ float sC[3][TJ];

    const int tid = threadIdx.x;
    const int w = tid >> 5;
    const int lane = tid & 31;
    const int g = lane >> 2;
    const int t = lane & 3;
    const int bh = blockIdx.y;
    const int b = bh >> 3, h = bh & 7;
    const int q0 = blockIdx.x * MQ;

    const float qscale = 0.14433756729740643f * LOG2E;
    const float wd2 = __ldg(W_dist + h) * LOG2E;

    const float* gKbase = qkv + (size_t)(b * NTOK) * QKV_COLS + D_MODEL + h * HEAD_DIM;
    const float* gVbase = gKbase + D_MODEL;

    float4 pK[3];
    float2 pV[6];
    float pC = 0.f;

    #pragma unroll
    for (int ii = 0; ii < 3; ii++) {
        const int idx = tid + 256 * ii;
        const int r = idx / 12, c4 = (idx % 12) * 4;
        pK[ii] = __ldg(reinterpret_cast<const float4*>(gKbase + (size_t)r * QKV_COLS + c4));
    }
    #pragma unroll
    for (int ii = 0; ii < 6; ii++) {
        const int i = tid + 256 * ii;
        const int kp = i / 48, d = i - kp * 48;
        pV[ii].x = __ldg(gVbase + (size_t)(2 * kp) * QKV_COLS + d);
        pV[ii].y = __ldg(gVbase + (size_t)(2 * kp + 1) * QKV_COLS + d);
    }
    if (tid < 192) {
        pC = __ldg(coords + (size_t)(b * NTOK + tid / 3) * 3 + (tid % 3));
    }

    uint32_t qh[2][3][4], ql[2][3][4];
    {
        const float* gQ = qkv + (size_t)(b * NTOK + q0) * QKV_COLS + h * HEAD_DIM;
        #pragma unroll
        for (int mt = 0; mt < 2; mt++) {
            const int rA = 32 * w + 16 * mt + g;
            #pragma unroll
            for (int kb = 0; kb < 3; kb++) {
                const int c = 16 * kb + 2 * t;
                float2 v0 = __ldg(reinterpret_cast<const float2*>(gQ + (size_t)rA * QKV_COLS + c));
                float2 v1 = __ldg(reinterpret_cast<const float2*>(gQ + (size_t)(rA + 8) * QKV_COLS + c));
                float2 v2 = __ldg(reinterpret_cast<const float2*>(gQ + (size_t)rA * QKV_COLS + c + 8));
                float2 v3 = __ldg(reinterpret_cast<const float2*>(gQ + (size_t)(rA + 8) * QKV_COLS + c + 8));
                split_pair(v0.x * qscale, v0.y * qscale, qh[mt][kb][0], ql[mt][kb][0]);
                split_pair(v1.x * qscale, v1.y * qscale, qh[mt][kb][1], ql[mt][kb][1]);
                split_pair(v2.x * qscale, v2.y * qscale, qh[mt][kb][2], ql[mt][kb][2]);
                split_pair(v3.x * qscale, v3.y * qscale, qh[mt][kb][3], ql[mt][kb][3]);
            }
        }
    }

    float qcx[4], qcy[4], qcz[4];
    #pragma unroll
    for (int rr = 0; rr < 4; rr++) {
        const int row = 32 * w + 8 * rr + g;
        const float* cp = coords + (size_t)(b * NTOK + q0 + row) * 3;
        qcx[rr] = __ldg(cp + 0); qcy[rr] = __ldg(cp + 1); qcz[rr] = __ldg(cp + 2);
    }

    float o[2][6][4];
    #pragma unroll
    for (int mt = 0; mt < 2; mt++)
        #pragma unroll
        for (int nb = 0; nb < 6; nb++)
            #pragma unroll
            for (int e = 0; e < 4; e++) o[mt][nb][e] = 0.f;

    float lsum[4] = {0.f, 0.f, 0.f, 0.f};

    for (int it = 0; it < N_ITERS; ++it) {
        __syncthreads();

        #pragma unroll
        for (int ii = 0; ii < 3; ii++) {
            const int idx = tid + 256 * ii;
            const int r = idx / 12, c4 = (idx % 12) * 4;
            uint32_t h0, l0, h1, l1;
            split_pair(pK[ii].x, pK[ii].y, h0, l0);
            split_pair(pK[ii].z, pK[ii].w, h1, l1);
            const int kwi = r * KSTR + (c4 >> 1);
            sKh[kwi] = h0; sKh[kwi + 1] = h1;
            sKl[kwi] = l0; sKl[kwi + 1] = l1;
        }
        #pragma unroll
        for (int ii = 0; ii < 6; ii++) {
            const int i = tid + 256 * ii;
            const int kp = i / 48, d = i - kp * 48;
            uint32_t hh, ll;
            split_pair(pV[ii].x, pV[ii].y, hh, ll);
            sVh[d * VSTR + kp] = hh;
            sVl[d * VSTR + kp] = ll;
        }
        if (tid < 192) sC[tid % 3][tid / 3] = pC;
        __syncthreads();

        if (it + 1 < N_ITERS) {
            const int j1 = (it + 1) * TJ;
            #pragma unroll
            for (int ii = 0; ii < 3; ii++) {
                const int idx = tid + 256 * ii;
                const int r = idx / 12, c4 = (idx % 12) * 4;
                pK[ii] = __ldg(reinterpret_cast<const float4*>(gKbase + (size_t)(j1 + r) * QKV_COLS + c4));
            }
            #pragma unroll
            for (int ii = 0; ii < 6; ii++) {
                const int i = tid + 256 * ii;
                const int kp = i / 48, d = i - kp * 48;
                pV[ii].x = __ldg(gVbase + (size_t)(j1 + 2 * kp) * QKV_COLS + d);
                pV[ii].y = __ldg(gVbase + (size_t)(j1 + 2 * kp + 1) * QKV_COLS + d);
            }
            if (tid < 192) {
                pC = __ldg(coords + (size_t)(b * NTOK + j1 + tid / 3) * 3 + (tid % 3));
            }
        }

        float s[2][8][4];
        #pragma unroll
        for (int mt = 0; mt < 2; mt++)
            #pragma unroll
            for (int nb = 0; nb < 8; nb++)
                #pragma unroll
                for (int e = 0; e < 4; e++) s[mt][nb][e] = 0.f;

        #pragma unroll
        for (int kb = 0; kb < 3; kb++) {
            #pragma unroll
            for (int nbp = 0; nbp < 4; nbp++) {
                const int nb0 = 2 * nbp, nb1 = 2 * nbp + 1;
                const int kb0 = (8 * nb0 + g) * KSTR + 8 * kb;
                const int kb1 = (8 * nb1 + g) * KSTR + 8 * kb;
                uint32_t b0h[2], b0l[2], b1h[2], b1l[2];
                b0h[0] = sKh[kb0 + t]; b0h[1] = sKh[kb0 + t + 4];
                b0l[0] = sKl[kb0 + t]; b0l[1] = sKl[kb0 + t + 4];
                b1h[0] = sKh[kb1 + t]; b1h[1] = sKh[kb1 + t + 4];
                b1l[0] = sKl[kb1 + t]; b1l[1] = sKl[kb1 + t + 4];
                mma_bf16(s[0][nb0], qh[0][kb], b0h);
                mma_bf16(s[0][nb1], qh[0][kb], b1h);
                mma_bf16(s[1][nb0], qh[1][kb], b0h);
                mma_bf16(s[1][nb1], qh[1][kb], b1h);
                mma_bf16(s[0][nb0], ql[0][kb], b0h);
                mma_bf16(s[0][nb1], ql[0][kb], b1h);
                mma_bf16(s[1][nb0], ql[1][kb], b0h);
                mma_bf16(s[1][nb1], ql[1][kb], b1h);
                mma_bf16(s[0][nb0], qh[0][kb], b0l);
                mma_bf16(s[0][nb1], qh[0][kb], b1l);
                mma_bf16(s[1][nb0], qh[1][kb], b0l);
                mma_bf16(s[1][nb1], qh[1][kb], b1l);
            }
        }

        #pragma unroll
        for (int kb = 0; kb < 4; kb++) {
            #pragma unroll
            for (int nbo = 0; nbo < 2; nbo++) {
                const int nb = 2 * kb + nbo;
                const int c0 = 8 * nb + 2 * t;
                const float kx0 = sC[0][c0], ky0 = sC[1][c0], kz0 = sC[2][c0];
                const float kx1 = sC[0][c0 + 1], ky1 = sC[1][c0 + 1], kz1 = sC[2][c0 + 1];
                #pragma unroll
                for (int mt = 0; mt < 2; mt++) {
                    #pragma unroll
                    for (int half = 0; half < 2; half++) {
                        const int rr = 2 * mt + half;
                        float dx0 = qcx[rr] - kx0, dy0 = qcy[rr] - ky0, dz0 = qcz[rr] - kz0;
                        float dx1 = qcx[rr] - kx1, dy1 = qcy[rr] - ky1, dz1 = qcz[rr] - kz1;
                        float d0 = sqrt_approx(fmaf(dx0, dx0, fmaf(dy0, dy0, dz0 * dz0)));
                        float d1 = sqrt_approx(fmaf(dx1, dx1, fmaf(dy1, dy1, dz1 * dz1)));
                        float p0 = ex2_approx(fmaf(wd2, d0, s[mt][nb][2 * half]));
                        float p1 = ex2_approx(fmaf(wd2, d1, s[mt][nb][2 * half + 1]));
                        s[mt][nb][2 * half] = p0;
                        s[mt][nb][2 * half + 1] = p1;
                        lsum[rr] += p0 + p1;
                    }
                }
            }
            uint32_t ah[2][4], al[2][4];
            #pragma unroll
            for (int mt = 0; mt < 2; mt++) {
                split_pair(s[mt][2 * kb][0],     s[mt][2 * kb][1],     ah[mt][0], al[mt][0]);
                split_pair(s[mt][2 * kb][2],     s[mt][2 * kb][3],     ah[mt][1], al[mt][1]);
                split_pair(s[mt][2 * kb + 1][0], s[mt][2 * kb + 1][1], ah[mt][2], al[mt][2]);
                split_pair(s[mt][2 * kb + 1][2], s[mt][2 * kb + 1][3], ah[mt][3], al[mt][3]);
            }
            #pragma unroll
            for (int nbp = 0; nbp < 3; nbp++) {
                const int nb0 = 2 * nbp, nb1 = 2 * nbp + 1;
                const int vb0 = (8 * nb0 + g) * VSTR + 8 * kb;
                const int vb1 = (8 * nb1 + g) * VSTR + 8 * kb;
                uint32_t v0h[2], v0l[2], v1h[2], v1l[2];
                v0h[0] = sVh[vb0 + t]; v0h[1] = sVh[vb0 + t + 4];
                v0l[0] = sVl[vb0 + t]; v0l[1] = sVl[vb0 + t + 4];
                v1h[0] = sVh[vb1 + t]; v1h[1] = sVh[vb1 + t + 4];
                v1l[0] = sVl[vb1 + t]; v1l[1] = sVl[vb1 + t + 4];
                mma_bf16(o[0][nb0], ah[0], v0h);
                mma_bf16(o[0][nb1], ah[0], v1h);
                mma_bf16(o[1][nb0], ah[1], v0h);
                mma_bf16(o[1][nb1], ah[1], v1h);
                mma_bf16(o[0][nb0], al[0], v0h);
                mma_bf16(o[0][nb1], al[0], v1h);
                mma_bf16(o[1][nb0], al[1], v0h);
                mma_bf16(o[1][nb1], al[1], v1h);
                mma_bf16(o[0][nb0], ah[0], v0l);
                mma_bf16(o[0][nb1], ah[0], v1l);
                mma_bf16(o[1][nb0], ah[1], v0l);
                mma_bf16(o[1][nb1], ah[1], v1l);
            }
        }
    }

    #pragma unroll
    for (int rr = 0; rr < 4; rr++) {
        lsum[rr] += __shfl_xor_sync(0xffffffffu, lsum[rr], 1);
        lsum[rr] += __shfl_xor_sync(0xffffffffu, lsum[rr], 2);
        lsum[rr] = 1.f / lsum[rr];
    }

    #pragma unroll
    for (int mt = 0; mt < 2; mt++) {
        const int rowA = 32 * w + 16 * mt + g;
        float* oA = out + (size_t)(b * NTOK + q0 + rowA) * D_MODEL + h * HEAD_DIM;
        float* oB = oA + (size_t)8 * D_MODEL;
        const float invA = lsum[2 * mt], invB = lsum[2 * mt + 1];
        #pragma unroll
        for (int nb = 0; nb < 6; nb++) {
            float2 vA = make_float2(o[mt][nb][0] * invA, o[mt][nb][1] * invA);
            float2 vB = make_float2(o[mt][nb][2] * invB, o[mt][nb][3] * invB);
            *reinterpret_cast<float2*>(oA + 8 * nb + 2 * t) = vA;
            *reinterpret_cast<float2*>(oB + 8 * nb + 2 * t) = vB;
        }
    }
}

// ---------------------------------------------------------------------------
extern "C" void kernel_launch(void* const* d_in, const int* in_sizes, int n_in,
                              void* d_out, int out_size)
{
    const float* x      = (const float*)d_in[0];
    const float* coords = (const float*)d_in[1];
    const float* W_qkv  = (const float*)d_in[2];
    const float* b_qkv  = (const float*)d_in[3];
    const float* W_dist = (const float*)d_in[4];
    const float* b_dist = (const float*)d_in[5];
    const float* W_out  = (const float*)d_in[6];
    const float* b_out  = (const float*)d_in[7];
    float* out = (float*)d_out;

    float* qkv_buf = nullptr;
    float* attn_buf = nullptr;
    cudaGetSymbolAddress((void**)&qkv_buf, g_qkv);
    cudaGetSymbolAddress((void**)&attn_buf, g_attn);

    // 1) QKV projection (3xBF16 MMA, prefetch-pipelined)
    {
        dim3 grid(QKV_COLS / GBN, TOTAL_TOK / GBM);
        gemm_bf16x3_kernel<<<grid, 256>>>(x, W_qkv, b_qkv, qkv_buf,
                                          TOTAL_TOK, QKV_COLS, D_MODEL);
    }

    // 2) fused attention (latency-engineered 3xBF16 warp mma)
    {
        dim3 grid(NTOK / MQ, BATCH * N_HEADS);
        attn_mma_kernel<<<grid, 256>>>(qkv_buf, coords, W_dist, b_dist, attn_buf);
    }

    // 3) Output projection (3xBF16 MMA, prefetch-pipelined)
    {
        dim3 grid(D_MODEL / GBN, TOTAL_TOK / GBM);
        gemm_bf16x3_kernel<<<grid, 256>>>(attn_buf, W_out, b_out, out,
                                          TOTAL_TOK, D_MODEL, D_MODEL);
    }
}

// round 9
// speedup vs baseline: 1.2032x; 1.2032x over previous
#include <cuda_runtime.h>
#include <cuda_bf16.h>
#include <cuda_fp16.h>
#include <cstdint>
#include <math.h>

#define D_MODEL 384
#define N_HEADS 8
#define HEAD_DIM 48
#define BATCH 2
#define NTOK 2048
#define TOTAL_TOK (BATCH * NTOK)
#define QKV_COLS (3 * D_MODEL)

// Scratch (allocation-free)
__device__ float g_qkv[TOTAL_TOK * QKV_COLS];
__device__ float g_attn[TOTAL_TOK * D_MODEL];

// ---------------------------------------------------------------------------
// helpers
// ---------------------------------------------------------------------------
__device__ __forceinline__ void mma_bf16(float* d, const uint32_t* a, const uint32_t* b) {
    asm volatile(
        "mma.sync.aligned.m16n8k16.row.col.f32.bf16.bf16.f32 "
        "{%0,%1,%2,%3}, {%4,%5,%6,%7}, {%8,%9}, {%0,%1,%2,%3};"
        : "+f"(d[0]), "+f"(d[1]), "+f"(d[2]), "+f"(d[3])
        : "r"(a[0]), "r"(a[1]), "r"(a[2]), "r"(a[3]), "r"(b[0]), "r"(b[1]));
}
__device__ __forceinline__ void mma_f16(float* d, const uint32_t* a, const uint32_t* b) {
    asm volatile(
        "mma.sync.aligned.m16n8k16.row.col.f32.f16.f16.f32 "
        "{%0,%1,%2,%3}, {%4,%5,%6,%7}, {%8,%9}, {%0,%1,%2,%3};"
        : "+f"(d[0]), "+f"(d[1]), "+f"(d[2]), "+f"(d[3])
        : "r"(a[0]), "r"(a[1]), "r"(a[2]), "r"(a[3]), "r"(b[0]), "r"(b[1]));
}

// pack two f32 -> bf16x2 / f16x2 (low half = first arg)
__device__ __forceinline__ uint32_t pack_bf16(float x, float y) {
    uint32_t r; asm("cvt.rn.bf16x2.f32 %0, %1, %2;" : "=r"(r) : "f"(y), "f"(x)); return r;
}
__device__ __forceinline__ void split_pair(float v0, float v1, uint32_t& hi, uint32_t& lo) {
    hi = pack_bf16(v0, v1);
    float h0 = __uint_as_float(hi << 16);
    float h1 = __uint_as_float(hi & 0xFFFF0000u);
    lo = pack_bf16(v0 - h0, v1 - h1);
}
__device__ __forceinline__ uint32_t pack_f16(float x, float y) {
    uint32_t r; asm("cvt.rn.f16x2.f32 %0, %1, %2;" : "=r"(r) : "f"(y), "f"(x)); return r;
}
__device__ __forceinline__ void split_pair_f16(float v0, float v1, uint32_t& hi, uint32_t& lo) {
    hi = pack_f16(v0, v1);
    __half2 h2 = *reinterpret_cast<__half2*>(&hi);
    float2 back = __half22float2(h2);
    lo = pack_f16(v0 - back.x, v1 - back.y);
}

__device__ __forceinline__ float sqrt_approx(float x) {
    float r; asm("sqrt.approx.f32 %0, %1;" : "=f"(r) : "f"(x)); return r;
}
__device__ __forceinline__ float ex2_approx(float x) {
    float r; asm("ex2.approx.f32 %0, %1;" : "=f"(r) : "f"(x)); return r;
}

// ---------------------------------------------------------------------------
// 3xBF16 tensor-core GEMM with bias (R6 config — fastest measured, 48.4us)
// ---------------------------------------------------------------------------
#define GBM 128
#define GBN 64
#define GBK 32
#define ASTR 20
#define BSTR 20

__global__ __launch_bounds__(256)
void gemm_bf16x3_kernel(const float* __restrict__ A, const float* __restrict__ B,
                        const float* __restrict__ bias, float* __restrict__ C,
                        int M, int N, int K)
{
    __shared__ uint32_t sAh[GBM * ASTR];
    __shared__ uint32_t sAl[GBM * ASTR];
    __shared__ uint32_t sBh[GBN * BSTR];
    __shared__ uint32_t sBl[GBN * BSTR];

    const int tid = threadIdx.x;
    const int w = tid >> 5;
    const int lane = tid & 31;
    const int g = lane >> 2;
    const int t = lane & 3;
    const int wm = w >> 1;
    const int wn = w & 1;
    const int row0 = blockIdx.y * GBM;
    const int col0 = blockIdx.x * GBN;

    float acc[2][4][4];
    #pragma unroll
    for (int mt = 0; mt < 2; mt++)
        #pragma unroll
        for (int nb = 0; nb < 4; nb++)
            #pragma unroll
            for (int e = 0; e < 4; e++) acc[mt][nb][e] = 0.f;

    for (int k0 = 0; k0 < K; k0 += GBK) {
        __syncthreads();
        #pragma unroll
        for (int i = tid; i < GBM * 8; i += 256) {
            const int r = i >> 3;
            const int j = i & 7;
            float4 v = __ldg(reinterpret_cast<const float4*>(A + (size_t)(row0 + r) * K + k0 + 4 * j));
            uint32_t h0, l0, h1, l1;
            split_pair(v.x, v.y, h0, l0);
            split_pair(v.z, v.w, h1, l1);
            const int base = r * ASTR + 2 * j;
            sAh[base] = h0; sAh[base + 1] = h1;
            sAl[base] = l0; sAl[base + 1] = l1;
        }
        #pragma unroll
        for (int i = tid; i < GBN * 16; i += 256) {
            const int n = i & 63;
            const int kp = i >> 6;
            float b0 = __ldg(B + (size_t)(k0 + 2 * kp) * N + col0 + n);
            float b1 = __ldg(B + (size_t)(k0 + 2 * kp + 1) * N + col0 + n);
            uint32_t hh, ll;
            split_pair(b0, b1, hh, ll);
            sBh[n * BSTR + kp] = hh;
            sBl[n * BSTR + kp] = ll;
        }
        __syncthreads();

        #pragma unroll
        for (int kc = 0; kc < 2; kc++) {
            uint32_t ah[2][4], al[2][4];
            #pragma unroll
            for (int mt = 0; mt < 2; mt++) {
                const int rA = (32 * wm + 16 * mt + g) * ASTR + 8 * kc;
                const int rB = rA + 8 * ASTR;
                ah[mt][0] = sAh[rA + t];     al[mt][0] = sAl[rA + t];
                ah[mt][1] = sAh[rB + t];     al[mt][1] = sAl[rB + t];
                ah[mt][2] = sAh[rA + t + 4]; al[mt][2] = sAl[rA + t + 4];
                ah[mt][3] = sAh[rB + t + 4]; al[mt][3] = sAl[rB + t + 4];
            }
            #pragma unroll
            for (int nb = 0; nb < 4; nb++) {
                const int nbase = (32 * wn + 8 * nb + g) * BSTR + 8 * kc;
                uint32_t bh_[2], bl_[2];
                bh_[0] = sBh[nbase + t];
                bh_[1] = sBh[nbase + t + 4];
                bl_[0] = sBl[nbase + t];
                bl_[1] = sBl[nbase + t + 4];
                mma_bf16(acc[0][nb], ah[0], bh_);
                mma_bf16(acc[1][nb], ah[1], bh_);
                mma_bf16(acc[0][nb], al[0], bh_);
                mma_bf16(acc[1][nb], al[1], bh_);
                mma_bf16(acc[0][nb], ah[0], bl_);
                mma_bf16(acc[1][nb], ah[1], bl_);
            }
        }
    }

    #pragma unroll
    for (int mt = 0; mt < 2; mt++) {
        const int rA = row0 + 32 * wm + 16 * mt + g;
        #pragma unroll
        for (int nb = 0; nb < 4; nb++) {
            const int c = col0 + 32 * wn + 8 * nb + 2 * t;
            const float bx = bias[c], by = bias[c + 1];
            *reinterpret_cast<float2*>(C + (size_t)rA * N + c) =
                make_float2(acc[mt][nb][0] + bx, acc[mt][nb][1] + by);
            *reinterpret_cast<float2*>(C + (size_t)(rA + 8) * N + c) =
                make_float2(acc[mt][nb][2] + bx, acc[mt][nb][3] + by);
        }
    }
}

// ---------------------------------------------------------------------------
// Fused attention: 2-term FP16 split mma.
//   S = (qh + ql) @ kh     (exact in q; only k rounded once to fp16)
//   O = (ph + pl) @ vh     (exact in p; only v rounded once to fp16)
// K/V staged hi-only (smem halved). Prefetch + interleave from R7 retained.
// ---------------------------------------------------------------------------
#define TJ 64
#define MQ 256
#define N_ITERS (NTOK / TJ)
#define KSTR 28
#define VSTR 36
#define LOG2E 1.4426950408889634f

__global__ __launch_bounds__(256, 1)
void attn_mma_kernel(const float* __restrict__ qkv, const float* __restrict__ coords,
                     const float* __restrict__ W_dist, const float* __restrict__ b_dist,
                     float* __restrict__ out)
{
    __shared__ uint32_t sKh[TJ * KSTR];
    __shared__ uint32_t sVh[HEAD_DIM * VSTR];
    __shared__ float sC[3][TJ];

    const int tid = threadIdx.x;
    const int w = tid >> 5;
    const int lane = tid & 31;
    const int g = lane >> 2;
    const int t = lane & 3;
    const int bh = blockIdx.y;
    const int b = bh >> 3, h = bh & 7;
    const int q0 = blockIdx.x * MQ;

    const float qscale = 0.14433756729740643f * LOG2E;
    const float wd2 = __ldg(W_dist + h) * LOG2E;

    const float* gKbase = qkv + (size_t)(b * NTOK) * QKV_COLS + D_MODEL + h * HEAD_DIM;
    const float* gVbase = gKbase + D_MODEL;

    float4 pK[3];
    float2 pV[6];
    float pC = 0.f;

    // ---- initial prefetch (tile 0) ----
    #pragma unroll
    for (int ii = 0; ii < 3; ii++) {
        const int idx = tid + 256 * ii;
        const int r = idx / 12, c4 = (idx % 12) * 4;
        pK[ii] = __ldg(reinterpret_cast<const float4*>(gKbase + (size_t)r * QKV_COLS + c4));
    }
    #pragma unroll
    for (int ii = 0; ii < 6; ii++) {
        const int i = tid + 256 * ii;
        const int kp = i / 48, d = i - kp * 48;
        pV[ii].x = __ldg(gVbase + (size_t)(2 * kp) * QKV_COLS + d);
        pV[ii].y = __ldg(gVbase + (size_t)(2 * kp + 1) * QKV_COLS + d);
    }
    if (tid < 192) {
        pC = __ldg(coords + (size_t)(b * NTOK + tid / 3) * 3 + (tid % 3));
    }

    // ---- Q fragments, fp16 hi/lo split (A-side carries the residual) ----
    uint32_t qh[2][3][4], ql[2][3][4];
    {
        const float* gQ = qkv + (size_t)(b * NTOK + q0) * QKV_COLS + h * HEAD_DIM;
        #pragma unroll
        for (int mt = 0; mt < 2; mt++) {
            const int rA = 32 * w + 16 * mt + g;
            #pragma unroll
            for (int kb = 0; kb < 3; kb++) {
                const int c = 16 * kb + 2 * t;
                float2 v0 = __ldg(reinterpret_cast<const float2*>(gQ + (size_t)rA * QKV_COLS + c));
                float2 v1 = __ldg(reinterpret_cast<const float2*>(gQ + (size_t)(rA + 8) * QKV_COLS + c));
                float2 v2 = __ldg(reinterpret_cast<const float2*>(gQ + (size_t)rA * QKV_COLS + c + 8));
                float2 v3 = __ldg(reinterpret_cast<const float2*>(gQ + (size_t)(rA + 8) * QKV_COLS + c + 8));
                split_pair_f16(v0.x * qscale, v0.y * qscale, qh[mt][kb][0], ql[mt][kb][0]);
                split_pair_f16(v1.x * qscale, v1.y * qscale, qh[mt][kb][1], ql[mt][kb][1]);
                split_pair_f16(v2.x * qscale, v2.y * qscale, qh[mt][kb][2], ql[mt][kb][2]);
                split_pair_f16(v3.x * qscale, v3.y * qscale, qh[mt][kb][3], ql[mt][kb][3]);
            }
        }
    }

    float qcx[4], qcy[4], qcz[4];
    #pragma unroll
    for (int rr = 0; rr < 4; rr++) {
        const int row = 32 * w + 8 * rr + g;
        const float* cp = coords + (size_t)(b * NTOK + q0 + row) * 3;
        qcx[rr] = __ldg(cp + 0); qcy[rr] = __ldg(cp + 1); qcz[rr] = __ldg(cp + 2);
    }

    float o[2][6][4];
    #pragma unroll
    for (int mt = 0; mt < 2; mt++)
        #pragma unroll
        for (int nb = 0; nb < 6; nb++)
            #pragma unroll
            for (int e = 0; e < 4; e++) o[mt][nb][e] = 0.f;

    float lsum[4] = {0.f, 0.f, 0.f, 0.f};

    for (int it = 0; it < N_ITERS; ++it) {
        __syncthreads();

        // ---- STS: pack prefetched tile to fp16-hi smem ----
        #pragma unroll
        for (int ii = 0; ii < 3; ii++) {
            const int idx = tid + 256 * ii;
            const int r = idx / 12, c4 = (idx % 12) * 4;
            const int kwi = r * KSTR + (c4 >> 1);
            sKh[kwi] = pack_f16(pK[ii].x, pK[ii].y);
            sKh[kwi + 1] = pack_f16(pK[ii].z, pK[ii].w);
        }
        #pragma unroll
        for (int ii = 0; ii < 6; ii++) {
            const int i = tid + 256 * ii;
            const int kp = i / 48, d = i - kp * 48;
            sVh[d * VSTR + kp] = pack_f16(pV[ii].x, pV[ii].y);
        }
        if (tid < 192) sC[tid % 3][tid / 3] = pC;
        __syncthreads();

        // ---- prefetch next tile (overlapped with compute below) ----
        if (it + 1 < N_ITERS) {
            const int j1 = (it + 1) * TJ;
            #pragma unroll
            for (int ii = 0; ii < 3; ii++) {
                const int idx = tid + 256 * ii;
                const int r = idx / 12, c4 = (idx % 12) * 4;
                pK[ii] = __ldg(reinterpret_cast<const float4*>(gKbase + (size_t)(j1 + r) * QKV_COLS + c4));
            }
            #pragma unroll
            for (int ii = 0; ii < 6; ii++) {
                const int i = tid + 256 * ii;
                const int kp = i / 48, d = i - kp * 48;
                pV[ii].x = __ldg(gVbase + (size_t)(j1 + 2 * kp) * QKV_COLS + d);
                pV[ii].y = __ldg(gVbase + (size_t)(j1 + 2 * kp + 1) * QKV_COLS + d);
            }
            if (tid < 192) {
                pC = __ldg(coords + (size_t)(b * NTOK + j1 + tid / 3) * 3 + (tid % 3));
            }
        }

        // ---- S = (qh+ql) @ kh ----
        float s[2][8][4];
        #pragma unroll
        for (int mt = 0; mt < 2; mt++)
            #pragma unroll
            for (int nb = 0; nb < 8; nb++)
                #pragma unroll
                for (int e = 0; e < 4; e++) s[mt][nb][e] = 0.f;

        #pragma unroll
        for (int kb = 0; kb < 3; kb++) {
            #pragma unroll
            for (int nbp = 0; nbp < 4; nbp++) {
                const int nb0 = 2 * nbp, nb1 = 2 * nbp + 1;
                const int kb0 = (8 * nb0 + g) * KSTR + 8 * kb;
                const int kb1 = (8 * nb1 + g) * KSTR + 8 * kb;
                uint32_t b0h[2], b1h[2];
                b0h[0] = sKh[kb0 + t]; b0h[1] = sKh[kb0 + t + 4];
                b1h[0] = sKh[kb1 + t]; b1h[1] = sKh[kb1 + t + 4];
                mma_f16(s[0][nb0], qh[0][kb], b0h);
                mma_f16(s[0][nb1], qh[0][kb], b1h);
                mma_f16(s[1][nb0], qh[1][kb], b0h);
                mma_f16(s[1][nb1], qh[1][kb], b1h);
                mma_f16(s[0][nb0], ql[0][kb], b0h);
                mma_f16(s[0][nb1], ql[0][kb], b1h);
                mma_f16(s[1][nb0], ql[1][kb], b0h);
                mma_f16(s[1][nb1], ql[1][kb], b1h);
            }
        }

        // ---- per key-chunk: softmax interleaved with PV ----
        #pragma unroll
        for (int kb = 0; kb < 4; kb++) {
            #pragma unroll
            for (int nbo = 0; nbo < 2; nbo++) {
                const int nb = 2 * kb + nbo;
                const int c0 = 8 * nb + 2 * t;
                const float kx0 = sC[0][c0], ky0 = sC[1][c0], kz0 = sC[2][c0];
                const float kx1 = sC[0][c0 + 1], ky1 = sC[1][c0 + 1], kz1 = sC[2][c0 + 1];
                #pragma unroll
                for (int mt = 0; mt < 2; mt++) {
                    #pragma unroll
                    for (int half = 0; half < 2; half++) {
                        const int rr = 2 * mt + half;
                        float dx0 = qcx[rr] - kx0, dy0 = qcy[rr] - ky0, dz0 = qcz[rr] - kz0;
                        float dx1 = qcx[rr] - kx1, dy1 = qcy[rr] - ky1, dz1 = qcz[rr] - kz1;
                        float d0 = sqrt_approx(fmaf(dx0, dx0, fmaf(dy0, dy0, dz0 * dz0)));
                        float d1 = sqrt_approx(fmaf(dx1, dx1, fmaf(dy1, dy1, dz1 * dz1)));
                        float p0 = ex2_approx(fmaf(wd2, d0, s[mt][nb][2 * half]));
                        float p1 = ex2_approx(fmaf(wd2, d1, s[mt][nb][2 * half + 1]));
                        s[mt][nb][2 * half] = p0;
                        s[mt][nb][2 * half + 1] = p1;
                        lsum[rr] += p0 + p1;
                    }
                }
            }
            // split P into fp16 hi/lo A-fragments
            uint32_t ah[2][4], al[2][4];
            #pragma unroll
            for (int mt = 0; mt < 2; mt++) {
                split_pair_f16(s[mt][2 * kb][0],     s[mt][2 * kb][1],     ah[mt][0], al[mt][0]);
                split_pair_f16(s[mt][2 * kb][2],     s[mt][2 * kb][3],     ah[mt][1], al[mt][1]);
                split_pair_f16(s[mt][2 * kb + 1][0], s[mt][2 * kb + 1][1], ah[mt][2], al[mt][2]);
                split_pair_f16(s[mt][2 * kb + 1][2], s[mt][2 * kb + 1][3], ah[mt][3], al[mt][3]);
            }
            // O += (ph+pl) @ vh
            #pragma unroll
            for (int nbp = 0; nbp < 3; nbp++) {
                const int nb0 = 2 * nbp, nb1 = 2 * nbp + 1;
                const int vb0 = (8 * nb0 + g) * VSTR + 8 * kb;
                const int vb1 = (8 * nb1 + g) * VSTR + 8 * kb;
                uint32_t v0h[2], v1h[2];
                v0h[0] = sVh[vb0 + t]; v0h[1] = sVh[vb0 + t + 4];
                v1h[0] = sVh[vb1 + t]; v1h[1] = sVh[vb1 + t + 4];
                mma_f16(o[0][nb0], ah[0], v0h);
                mma_f16(o[0][nb1], ah[0], v1h);
                mma_f16(o[1][nb0], ah[1], v0h);
                mma_f16(o[1][nb1], ah[1], v1h);
                mma_f16(o[0][nb0], al[0], v0h);
                mma_f16(o[0][nb1], al[0], v1h);
                mma_f16(o[1][nb0], al[1], v0h);
                mma_f16(o[1][nb1], al[1], v1h);
            }
        }
    }

    // ---- finalize ----
    #pragma unroll
    for (int rr = 0; rr < 4; rr++) {
        lsum[rr] += __shfl_xor_sync(0xffffffffu, lsum[rr], 1);
        lsum[rr] += __shfl_xor_sync(0xffffffffu, lsum[rr], 2);
        lsum[rr] = 1.f / lsum[rr];
    }

    #pragma unroll
    for (int mt = 0; mt < 2; mt++) {
        const int rowA = 32 * w + 16 * mt + g;
        float* oA = out + (size_t)(b * NTOK + q0 + rowA) * D_MODEL + h * HEAD_DIM;
        float* oB = oA + (size_t)8 * D_MODEL;
        const float invA = lsum[2 * mt], invB = lsum[2 * mt + 1];
        #pragma unroll
        for (int nb = 0; nb < 6; nb++) {
            float2 vA = make_float2(o[mt][nb][0] * invA, o[mt][nb][1] * invA);
            float2 vB = make_float2(o[mt][nb][2] * invB, o[mt][nb][3] * invB);
            *reinterpret_cast<float2*>(oA + 8 * nb + 2 * t) = vA;
            *reinterpret_cast<float2*>(oB + 8 * nb + 2 * t) = vB;
        }
    }
}

// ---------------------------------------------------------------------------
extern "C" void kernel_launch(void* const* d_in, const int* in_sizes, int n_in,
                              void* d_out, int out_size)
{
    const float* x      = (const float*)d_in[0];
    const float* coords = (const float*)d_in[1];
    const float* W_qkv  = (const float*)d_in[2];
    const float* b_qkv  = (const float*)d_in[3];
    const float* W_dist = (const float*)d_in[4];
    const float* b_dist = (const float*)d_in[5];
    const float* W_out  = (const float*)d_in[6];
    const float* b_out  = (const float*)d_in[7];
    float* out = (float*)d_out;

    float* qkv_buf = nullptr;
    float* attn_buf = nullptr;
    cudaGetSymbolAddress((void**)&qkv_buf, g_qkv);
    cudaGetSymbolAddress((void**)&attn_buf, g_attn);

    // 1) QKV projection (3xBF16 MMA)
    {
        dim3 grid(QKV_COLS / GBN, TOTAL_TOK / GBM);
        gemm_bf16x3_kernel<<<grid, 256>>>(x, W_qkv, b_qkv, qkv_buf,
                                          TOTAL_TOK, QKV_COLS, D_MODEL);
    }

    // 2) fused attention (2-term FP16 warp mma)
    {
        dim3 grid(NTOK / MQ, BATCH * N_HEADS);
        attn_mma_kernel<<<grid, 256>>>(qkv_buf, coords, W_dist, b_dist, attn_buf);
    }

    // 3) Output projection (3xBF16 MMA)
    {
        dim3 grid(D_MODEL / GBN, TOTAL_TOK / GBM);
        gemm_bf16x3_kernel<<<grid, 256>>>(attn_buf, W_out, b_out, out,
                                          TOTAL_TOK, D_MODEL, D_MODEL);
    }
}

// round 10
// speedup vs baseline: 1.6589x; 1.3788x over previous
#include <cuda_runtime.h>
#include <cuda_bf16.h>
#include <cuda_fp16.h>
#include <cstdint>
#include <math.h>

#define D_MODEL 384
#define N_HEADS 8
#define HEAD_DIM 48
#define BATCH 2
#define NTOK 2048
#define TOTAL_TOK (BATCH * NTOK)
#define QKV_COLS (3 * D_MODEL)

// Scratch (allocation-free)
__device__ float g_qkv[TOTAL_TOK * QKV_COLS];
__device__ float g_attn[TOTAL_TOK * D_MODEL];

// ---------------------------------------------------------------------------
// helpers
// ---------------------------------------------------------------------------
__device__ __forceinline__ void mma_f16(float* d, const uint32_t* a, const uint32_t* b) {
    asm volatile(
        "mma.sync.aligned.m16n8k16.row.col.f32.f16.f16.f32 "
        "{%0,%1,%2,%3}, {%4,%5,%6,%7}, {%8,%9}, {%0,%1,%2,%3};"
        : "+f"(d[0]), "+f"(d[1]), "+f"(d[2]), "+f"(d[3])
        : "r"(a[0]), "r"(a[1]), "r"(a[2]), "r"(a[3]), "r"(b[0]), "r"(b[1]));
}

__device__ __forceinline__ uint32_t pack_f16(float x, float y) {
    uint32_t r; asm("cvt.rn.f16x2.f32 %0, %1, %2;" : "=r"(r) : "f"(y), "f"(x)); return r;
}
__device__ __forceinline__ void split_pair_f16(float v0, float v1, uint32_t& hi, uint32_t& lo) {
    hi = pack_f16(v0, v1);
    __half2 h2 = *reinterpret_cast<__half2*>(&hi);
    float2 back = __half22float2(h2);
    lo = pack_f16(v0 - back.x, v1 - back.y);
}

__device__ __forceinline__ float sqrt_approx(float x) {
    float r; asm("sqrt.approx.f32 %0, %1;" : "=f"(r) : "f"(x)); return r;
}
__device__ __forceinline__ float ex2_approx(float x) {
    float r; asm("ex2.approx.f32 %0, %1;" : "=f"(r) : "f"(x)); return r;
}

// ---------------------------------------------------------------------------
// 2-term FP16 tensor-core GEMM with bias:
//   C = (Ah + Al) @ Bh + bias   (A exact via hi/lo split; B rounded once)
// BM=128, BN=64, BK=32; 256 threads (8 warps, 4x2); warp tile 32x32.
// ---------------------------------------------------------------------------
#define GBM 128
#define GBN 64
#define GBK 32
#define ASTR 20
#define BSTR 20

__global__ __launch_bounds__(256)
void gemm_f16x2_kernel(const float* __restrict__ A, const float* __restrict__ B,
                       const float* __restrict__ bias, float* __restrict__ C,
                       int M, int N, int K)
{
    __shared__ uint32_t sAh[GBM * ASTR];
    __shared__ uint32_t sAl[GBM * ASTR];
    __shared__ uint32_t sBh[GBN * BSTR];

    const int tid = threadIdx.x;
    const int w = tid >> 5;
    const int lane = tid & 31;
    const int g = lane >> 2;
    const int t = lane & 3;
    const int wm = w >> 1;
    const int wn = w & 1;
    const int row0 = blockIdx.y * GBM;
    const int col0 = blockIdx.x * GBN;

    float acc[2][4][4];
    #pragma unroll
    for (int mt = 0; mt < 2; mt++)
        #pragma unroll
        for (int nb = 0; nb < 4; nb++)
            #pragma unroll
            for (int e = 0; e < 4; e++) acc[mt][nb][e] = 0.f;

    for (int k0 = 0; k0 < K; k0 += GBK) {
        __syncthreads();
        #pragma unroll
        for (int i = tid; i < GBM * 8; i += 256) {
            const int r = i >> 3;
            const int j = i & 7;
            float4 v = __ldg(reinterpret_cast<const float4*>(A + (size_t)(row0 + r) * K + k0 + 4 * j));
            uint32_t h0, l0, h1, l1;
            split_pair_f16(v.x, v.y, h0, l0);
            split_pair_f16(v.z, v.w, h1, l1);
            const int base = r * ASTR + 2 * j;
            sAh[base] = h0; sAh[base + 1] = h1;
            sAl[base] = l0; sAl[base + 1] = l1;
        }
        #pragma unroll
        for (int i = tid; i < GBN * 16; i += 256) {
            const int n = i & 63;
            const int kp = i >> 6;
            float b0 = __ldg(B + (size_t)(k0 + 2 * kp) * N + col0 + n);
            float b1 = __ldg(B + (size_t)(k0 + 2 * kp + 1) * N + col0 + n);
            sBh[n * BSTR + kp] = pack_f16(b0, b1);
        }
        __syncthreads();

        #pragma unroll
        for (int kc = 0; kc < 2; kc++) {
            uint32_t ah[2][4], al[2][4];
            #pragma unroll
            for (int mt = 0; mt < 2; mt++) {
                const int rA = (32 * wm + 16 * mt + g) * ASTR + 8 * kc;
                const int rB = rA + 8 * ASTR;
                ah[mt][0] = sAh[rA + t];     al[mt][0] = sAl[rA + t];
                ah[mt][1] = sAh[rB + t];     al[mt][1] = sAl[rB + t];
                ah[mt][2] = sAh[rA + t + 4]; al[mt][2] = sAl[rA + t + 4];
                ah[mt][3] = sAh[rB + t + 4]; al[mt][3] = sAl[rB + t + 4];
            }
            #pragma unroll
            for (int nb = 0; nb < 4; nb++) {
                const int nbase = (32 * wn + 8 * nb + g) * BSTR + 8 * kc;
                uint32_t bh_[2];
                bh_[0] = sBh[nbase + t];
                bh_[1] = sBh[nbase + t + 4];
                mma_f16(acc[0][nb], ah[0], bh_);
                mma_f16(acc[1][nb], ah[1], bh_);
                mma_f16(acc[0][nb], al[0], bh_);
                mma_f16(acc[1][nb], al[1], bh_);
            }
        }
    }

    #pragma unroll
    for (int mt = 0; mt < 2; mt++) {
        const int rA = row0 + 32 * wm + 16 * mt + g;
        #pragma unroll
        for (int nb = 0; nb < 4; nb++) {
            const int c = col0 + 32 * wn + 8 * nb + 2 * t;
            const float bx = bias[c], by = bias[c + 1];
            *reinterpret_cast<float2*>(C + (size_t)rA * N + c) =
                make_float2(acc[mt][nb][0] + bx, acc[mt][nb][1] + by);
            *reinterpret_cast<float2*>(C + (size_t)(rA + 8) * N + c) =
                make_float2(acc[mt][nb][2] + bx, acc[mt][nb][3] + by);
        }
    }
}

// ---------------------------------------------------------------------------
// Fused attention: single-term FP16 mma (error dominated by v-rounding,
// ~1.4e-4; q/k rounding contributes ~2e-5 via the 1/sqrt(d) logit scale).
// Prefetch double-buffering + softmax/PV interleave retained from R7.
// ---------------------------------------------------------------------------
#define TJ 64
#define MQ 256
#define N_ITERS (NTOK / TJ)
#define KSTR 28
#define VSTR 36
#define LOG2E 1.4426950408889634f

__global__ __launch_bounds__(256, 1)
void attn_mma_kernel(const float* __restrict__ qkv, const float* __restrict__ coords,
                     const float* __restrict__ W_dist, const float* __restrict__ b_dist,
                     float* __restrict__ out)
{
    __shared__ uint32_t sKh[TJ * KSTR];
    __shared__ uint32_t sVh[HEAD_DIM * VSTR];
    __shared__ float sC[3][TJ];

    const int tid = threadIdx.x;
    const int w = tid >> 5;
    const int lane = tid & 31;
    const int g = lane >> 2;
    const int t = lane & 3;
    const int bh = blockIdx.y;
    const int b = bh >> 3, h = bh & 7;
    const int q0 = blockIdx.x * MQ;

    const float qscale = 0.14433756729740643f * LOG2E;
    const float wd2 = __ldg(W_dist + h) * LOG2E;

    const float* gKbase = qkv + (size_t)(b * NTOK) * QKV_COLS + D_MODEL + h * HEAD_DIM;
    const float* gVbase = gKbase + D_MODEL;

    float4 pK[3];
    float2 pV[6];
    float pC = 0.f;

    // ---- initial prefetch (tile 0) ----
    #pragma unroll
    for (int ii = 0; ii < 3; ii++) {
        const int idx = tid + 256 * ii;
        const int r = idx / 12, c4 = (idx % 12) * 4;
        pK[ii] = __ldg(reinterpret_cast<const float4*>(gKbase + (size_t)r * QKV_COLS + c4));
    }
    #pragma unroll
    for (int ii = 0; ii < 6; ii++) {
        const int i = tid + 256 * ii;
        const int kp = i / 48, d = i - kp * 48;
        pV[ii].x = __ldg(gVbase + (size_t)(2 * kp) * QKV_COLS + d);
        pV[ii].y = __ldg(gVbase + (size_t)(2 * kp + 1) * QKV_COLS + d);
    }
    if (tid < 192) {
        pC = __ldg(coords + (size_t)(b * NTOK + tid / 3) * 3 + (tid % 3));
    }

    // ---- Q fragments, single fp16 (pre-scaled) ----
    uint32_t qh[2][3][4];
    {
        const float* gQ = qkv + (size_t)(b * NTOK + q0) * QKV_COLS + h * HEAD_DIM;
        #pragma unroll
        for (int mt = 0; mt < 2; mt++) {
            const int rA = 32 * w + 16 * mt + g;
            #pragma unroll
            for (int kb = 0; kb < 3; kb++) {
                const int c = 16 * kb + 2 * t;
                float2 v0 = __ldg(reinterpret_cast<const float2*>(gQ + (size_t)rA * QKV_COLS + c));
                float2 v1 = __ldg(reinterpret_cast<const float2*>(gQ + (size_t)(rA + 8) * QKV_COLS + c));
                float2 v2 = __ldg(reinterpret_cast<const float2*>(gQ + (size_t)rA * QKV_COLS + c + 8));
                float2 v3 = __ldg(reinterpret_cast<const float2*>(gQ + (size_t)(rA + 8) * QKV_COLS + c + 8));
                qh[mt][kb][0] = pack_f16(v0.x * qscale, v0.y * qscale);
                qh[mt][kb][1] = pack_f16(v1.x * qscale, v1.y * qscale);
                qh[mt][kb][2] = pack_f16(v2.x * qscale, v2.y * qscale);
                qh[mt][kb][3] = pack_f16(v3.x * qscale, v3.y * qscale);
            }
        }
    }

    float qcx[4], qcy[4], qcz[4];
    #pragma unroll
    for (int rr = 0; rr < 4; rr++) {
        const int row = 32 * w + 8 * rr + g;
        const float* cp = coords + (size_t)(b * NTOK + q0 + row) * 3;
        qcx[rr] = __ldg(cp + 0); qcy[rr] = __ldg(cp + 1); qcz[rr] = __ldg(cp + 2);
    }

    float o[2][6][4];
    #pragma unroll
    for (int mt = 0; mt < 2; mt++)
        #pragma unroll
        for (int nb = 0; nb < 6; nb++)
            #pragma unroll
            for (int e = 0; e < 4; e++) o[mt][nb][e] = 0.f;

    float lsum[4] = {0.f, 0.f, 0.f, 0.f};

    for (int it = 0; it < N_ITERS; ++it) {
        __syncthreads();

        // ---- STS: pack prefetched tile to fp16 smem ----
        #pragma unroll
        for (int ii = 0; ii < 3; ii++) {
            const int idx = tid + 256 * ii;
            const int r = idx / 12, c4 = (idx % 12) * 4;
            const int kwi = r * KSTR + (c4 >> 1);
            sKh[kwi] = pack_f16(pK[ii].x, pK[ii].y);
            sKh[kwi + 1] = pack_f16(pK[ii].z, pK[ii].w);
        }
        #pragma unroll
        for (int ii = 0; ii < 6; ii++) {
            const int i = tid + 256 * ii;
            const int kp = i / 48, d = i - kp * 48;
            sVh[d * VSTR + kp] = pack_f16(pV[ii].x, pV[ii].y);
        }
        if (tid < 192) sC[tid % 3][tid / 3] = pC;
        __syncthreads();

        // ---- prefetch next tile ----
        if (it + 1 < N_ITERS) {
            const int j1 = (it + 1) * TJ;
            #pragma unroll
            for (int ii = 0; ii < 3; ii++) {
                const int idx = tid + 256 * ii;
                const int r = idx / 12, c4 = (idx % 12) * 4;
                pK[ii] = __ldg(reinterpret_cast<const float4*>(gKbase + (size_t)(j1 + r) * QKV_COLS + c4));
            }
            #pragma unroll
            for (int ii = 0; ii < 6; ii++) {
                const int i = tid + 256 * ii;
                const int kp = i / 48, d = i - kp * 48;
                pV[ii].x = __ldg(gVbase + (size_t)(j1 + 2 * kp) * QKV_COLS + d);
                pV[ii].y = __ldg(gVbase + (size_t)(j1 + 2 * kp + 1) * QKV_COLS + d);
            }
            if (tid < 192) {
                pC = __ldg(coords + (size_t)(b * NTOK + j1 + tid / 3) * 3 + (tid % 3));
            }
        }

        // ---- S = qh @ kh (single fp16) ----
        float s[2][8][4];
        #pragma unroll
        for (int mt = 0; mt < 2; mt++)
            #pragma unroll
            for (int nb = 0; nb < 8; nb++)
                #pragma unroll
                for (int e = 0; e < 4; e++) s[mt][nb][e] = 0.f;

        #pragma unroll
        for (int kb = 0; kb < 3; kb++) {
            #pragma unroll
            for (int nbp = 0; nbp < 4; nbp++) {
                const int nb0 = 2 * nbp, nb1 = 2 * nbp + 1;
                const int kb0 = (8 * nb0 + g) * KSTR + 8 * kb;
                const int kb1 = (8 * nb1 + g) * KSTR + 8 * kb;
                uint32_t b0h[2], b1h[2];
                b0h[0] = sKh[kb0 + t]; b0h[1] = sKh[kb0 + t + 4];
                b1h[0] = sKh[kb1 + t]; b1h[1] = sKh[kb1 + t + 4];
                mma_f16(s[0][nb0], qh[0][kb], b0h);
                mma_f16(s[0][nb1], qh[0][kb], b1h);
                mma_f16(s[1][nb0], qh[1][kb], b0h);
                mma_f16(s[1][nb1], qh[1][kb], b1h);
            }
        }

        // ---- per key-chunk: softmax interleaved with PV ----
        #pragma unroll
        for (int kb = 0; kb < 4; kb++) {
            #pragma unroll
            for (int nbo = 0; nbo < 2; nbo++) {
                const int nb = 2 * kb + nbo;
                const int c0 = 8 * nb + 2 * t;
                const float kx0 = sC[0][c0], ky0 = sC[1][c0], kz0 = sC[2][c0];
                const float kx1 = sC[0][c0 + 1], ky1 = sC[1][c0 + 1], kz1 = sC[2][c0 + 1];
                #pragma unroll
                for (int mt = 0; mt < 2; mt++) {
                    #pragma unroll
                    for (int half = 0; half < 2; half++) {
                        const int rr = 2 * mt + half;
                        float dx0 = qcx[rr] - kx0, dy0 = qcy[rr] - ky0, dz0 = qcz[rr] - kz0;
                        float dx1 = qcx[rr] - kx1, dy1 = qcy[rr] - ky1, dz1 = qcz[rr] - kz1;
                        float d0 = sqrt_approx(fmaf(dx0, dx0, fmaf(dy0, dy0, dz0 * dz0)));
                        float d1 = sqrt_approx(fmaf(dx1, dx1, fmaf(dy1, dy1, dz1 * dz1)));
                        float p0 = ex2_approx(fmaf(wd2, d0, s[mt][nb][2 * half]));
                        float p1 = ex2_approx(fmaf(wd2, d1, s[mt][nb][2 * half + 1]));
                        s[mt][nb][2 * half] = p0;
                        s[mt][nb][2 * half + 1] = p1;
                        lsum[rr] += p0 + p1;
                    }
                }
            }
            // pack P into fp16 A-fragments (single term)
            uint32_t ah[2][4];
            #pragma unroll
            for (int mt = 0; mt < 2; mt++) {
                ah[mt][0] = pack_f16(s[mt][2 * kb][0],     s[mt][2 * kb][1]);
                ah[mt][1] = pack_f16(s[mt][2 * kb][2],     s[mt][2 * kb][3]);
                ah[mt][2] = pack_f16(s[mt][2 * kb + 1][0], s[mt][2 * kb + 1][1]);
                ah[mt][3] = pack_f16(s[mt][2 * kb + 1][2], s[mt][2 * kb + 1][3]);
            }
            // O += ph @ vh
            #pragma unroll
            for (int nbp = 0; nbp < 3; nbp++) {
                const int nb0 = 2 * nbp, nb1 = 2 * nbp + 1;
                const int vb0 = (8 * nb0 + g) * VSTR + 8 * kb;
                const int vb1 = (8 * nb1 + g) * VSTR + 8 * kb;
                uint32_t v0h[2], v1h[2];
                v0h[0] = sVh[vb0 + t]; v0h[1] = sVh[vb0 + t + 4];
                v1h[0] = sVh[vb1 + t]; v1h[1] = sVh[vb1 + t + 4];
                mma_f16(o[0][nb0], ah[0], v0h);
                mma_f16(o[0][nb1], ah[0], v1h);
                mma_f16(o[1][nb0], ah[1], v0h);
                mma_f16(o[1][nb1], ah[1], v1h);
            }
        }
    }

    // ---- finalize ----
    #pragma unroll
    for (int rr = 0; rr < 4; rr++) {
        lsum[rr] += __shfl_xor_sync(0xffffffffu, lsum[rr], 1);
        lsum[rr] += __shfl_xor_sync(0xffffffffu, lsum[rr], 2);
        lsum[rr] = 1.f / lsum[rr];
    }

    #pragma unroll
    for (int mt = 0; mt < 2; mt++) {
        const int rowA = 32 * w + 16 * mt + g;
        float* oA = out + (size_t)(b * NTOK + q0 + rowA) * D_MODEL + h * HEAD_DIM;
        float* oB = oA + (size_t)8 * D_MODEL;
        const float invA = lsum[2 * mt], invB = lsum[2 * mt + 1];
        #pragma unroll
        for (int nb = 0; nb < 6; nb++) {
            float2 vA = make_float2(o[mt][nb][0] * invA, o[mt][nb][1] * invA);
            float2 vB = make_float2(o[mt][nb][2] * invB, o[mt][nb][3] * invB);
            *reinterpret_cast<float2*>(oA + 8 * nb + 2 * t) = vA;
            *reinterpret_cast<float2*>(oB + 8 * nb + 2 * t) = vB;
        }
    }
}

// ---------------------------------------------------------------------------
extern "C" void kernel_launch(void* const* d_in, const int* in_sizes, int n_in,
                              void* d_out, int out_size)
{
    const float* x      = (const float*)d_in[0];
    const float* coords = (const float*)d_in[1];
    const float* W_qkv  = (const float*)d_in[2];
    const float* b_qkv  = (const float*)d_in[3];
    const float* W_dist = (const float*)d_in[4];
    const float* b_dist = (const float*)d_in[5];
    const float* W_out  = (const float*)d_in[6];
    const float* b_out  = (const float*)d_in[7];
    float* out = (float*)d_out;

    float* qkv_buf = nullptr;
    float* attn_buf = nullptr;
    cudaGetSymbolAddress((void**)&qkv_buf, g_qkv);
    cudaGetSymbolAddress((void**)&attn_buf, g_attn);

    // 1) QKV projection (2-term FP16 MMA)
    {
        dim3 grid(QKV_COLS / GBN, TOTAL_TOK / GBM);
        gemm_f16x2_kernel<<<grid, 256>>>(x, W_qkv, b_qkv, qkv_buf,
                                         TOTAL_TOK, QKV_COLS, D_MODEL);
    }

    // 2) fused attention (single-term FP16 warp mma)
    {
        dim3 grid(NTOK / MQ, BATCH * N_HEADS);
        attn_mma_kernel<<<grid, 256>>>(qkv_buf, coords, W_dist, b_dist, attn_buf);
    }

    // 3) Output projection (2-term FP16 MMA)
    {
        dim3 grid(D_MODEL / GBN, TOTAL_TOK / GBM);
        gemm_f16x2_kernel<<<grid, 256>>>(attn_buf, W_out, b_out, out,
                                         TOTAL_TOK, D_MODEL, D_MODEL);
    }
}